// round 1
// baseline (speedup 1.0000x reference)
#include <cuda_runtime.h>
#include <cstdint>

// ---------------------------------------------------------------------------
// RelGraphEmbedLayer:
//   out[i] = feat0[type_ids[i]] @ W0           if node_tids[i] == 0
//   out[i] = node_embed_table[node_ids[i]]      if node_tids[i] == 1
//
// Strategy:
//   K0: detect index dtype (int64 vs int32) + reset compaction counter
//   K1: warp-aggregated compaction of tid==0 nodes + fused embedding copy
//   K2: tiled fp32 GEMM over compacted nodes (64x128 tile, K=256)
// ---------------------------------------------------------------------------

#define D_IN   256
#define EMBED  128
#define TILE_M 64

__device__ int g_count;
__device__ int g_is64;
__device__ int g_compact[1100000];   // capacity >= N

// Read index i from a buffer that is either int64 or int32, per g_is64.
__device__ __forceinline__ long long load_idx(const void* p, int i, int is64) {
    if (is64) return ((const long long*)p)[i];
    return (long long)((const int*)p)[i];
}

// ---------------------------------------------------------------------------
// K0: single thread. Detect dtype of index arrays and reset counter.
// If node_ids is int64, every odd 32-bit word is 0 (ids < 2^20 << 2^32).
// If int32, odd words are random ids in [0,1e6) -> all-zero prob ~1e-48.
// ---------------------------------------------------------------------------
__global__ void k0_detect_reset(const void* node_ids) {
    const unsigned* w = (const unsigned*)node_ids;
    int is64 = 1;
    #pragma unroll
    for (int k = 0; k < 8; ++k)
        if (w[2 * k + 1] != 0u) { is64 = 0; break; }
    g_is64 = is64;
    g_count = 0;
}

// ---------------------------------------------------------------------------
// K1: block handles 256 consecutive nodes.
//  Part A: warp-ballot compaction of tid==0 nodes (1 atomic per warp).
//  Part B: warp-per-node float4 copy of embedding rows for tid==1 nodes.
// ---------------------------------------------------------------------------
__global__ __launch_bounds__(256) void k1_compact_embed(
    const void* __restrict__ node_ids,
    const void* __restrict__ node_tids,
    const float* __restrict__ table,
    float* __restrict__ out,
    int N)
{
    const int is64 = g_is64;
    const int base = blockIdx.x * 256;
    const int t    = threadIdx.x;
    const int lane = t & 31;
    const int wid  = t >> 5;
    const int i    = base + t;

    // ---- Part A: compaction ----
    bool is0 = false;
    if (i < N) is0 = (load_idx(node_tids, i, is64) == 0);
    unsigned m = __ballot_sync(0xffffffffu, is0);
    int cnt  = __popc(m);
    int rank = __popc(m & ((1u << lane) - 1u));
    int wbase = 0;
    if (lane == 0 && cnt) wbase = atomicAdd(&g_count, cnt);
    wbase = __shfl_sync(0xffffffffu, wbase, 0);
    if (is0) g_compact[wbase + rank] = i;

    // ---- Part B: embedding copy, warp per node ----
    #pragma unroll
    for (int j = wid; j < 256; j += 8) {
        int ii = base + j;
        if (ii < N) {
            if (load_idx(node_tids, ii, is64) == 1) {
                long long nid = load_idx(node_ids, ii, is64);
                const float4* src = (const float4*)(table + nid * (long long)EMBED);
                float4*       dst = (float4*)(out + (long long)ii * EMBED);
                dst[lane] = src[lane];
            }
        }
    }
}

// ---------------------------------------------------------------------------
// K2: projection GEMM over compacted tid==0 nodes.
//   Tile: M=64 nodes x N=128 outputs, K=256 in steps of 16.
//   256 threads: thread (ty = t/32 in 0..7, tx = t%32)
//   computes acc[8][4] -> rows m = ty + 8*r, cols n = tx*4 .. tx*4+3.
//   As stored transposed [k][m] with pad to kill store bank conflicts;
//   reads of As are warp-broadcast, reads of Bs are conflict-free LDS.128.
// ---------------------------------------------------------------------------
__global__ __launch_bounds__(256) void k2_proj_gemm(
    const void*  __restrict__ type_ids,
    const float* __restrict__ feat0,
    const float* __restrict__ W0,
    float* __restrict__ out)
{
    __shared__ float As[16][TILE_M + 1];   // [k][m], padded
    __shared__ float Bs[16][EMBED];        // [k][n]
    __shared__ int   s_cidx[TILE_M];       // original node index (output row)
    __shared__ int   s_ridx[TILE_M];       // feat0 row index

    const int count = g_count;
    const int m0 = blockIdx.x * TILE_M;
    if (m0 >= count) return;
    const int rows = min(TILE_M, count - m0);

    const int is64 = g_is64;
    const int t  = threadIdx.x;
    const int tx = t & 31;
    const int ty = t >> 5;

    if (t < TILE_M) {
        int src = (t < rows) ? (m0 + t) : m0;      // pad with dup of row 0
        int cidx = g_compact[src];
        s_cidx[t] = cidx;
        s_ridx[t] = (int)load_idx(type_ids, cidx, is64);
    }
    __syncthreads();

    // A-load mapping: thread t loads one float4 of row (t/4), segment (t%4)
    const int arow = t >> 2;        // 0..63
    const int aseg = t & 3;         // 0..3
    const float* aptr = feat0 + (long long)s_ridx[arow] * D_IN + aseg * 4;

    // B-load mapping: thread t loads k-rows (t/32) and (t/32 + 8), cols tx*4
    const int brow = ty;            // 0..7
    const int bcol = tx * 4;

    float acc[8][4];
    #pragma unroll
    for (int r = 0; r < 8; ++r)
        #pragma unroll
        for (int c = 0; c < 4; ++c) acc[r][c] = 0.0f;

    for (int kk = 0; kk < D_IN; kk += 16) {
        // stage A (gathered) and B tiles
        float4 av = *(const float4*)(aptr + kk);
        As[aseg * 4 + 0][arow] = av.x;
        As[aseg * 4 + 1][arow] = av.y;
        As[aseg * 4 + 2][arow] = av.z;
        As[aseg * 4 + 3][arow] = av.w;

        float4 b0 = *(const float4*)(W0 + (long long)(kk + brow) * EMBED + bcol);
        float4 b1 = *(const float4*)(W0 + (long long)(kk + brow + 8) * EMBED + bcol);
        *(float4*)&Bs[brow][bcol]     = b0;
        *(float4*)&Bs[brow + 8][bcol] = b1;
        __syncthreads();

        #pragma unroll
        for (int k = 0; k < 16; ++k) {
            float4 b = *(const float4*)&Bs[k][tx * 4];
            #pragma unroll
            for (int r = 0; r < 8; ++r) {
                float a = As[k][ty + 8 * r];
                acc[r][0] = fmaf(a, b.x, acc[r][0]);
                acc[r][1] = fmaf(a, b.y, acc[r][1]);
                acc[r][2] = fmaf(a, b.z, acc[r][2]);
                acc[r][3] = fmaf(a, b.w, acc[r][3]);
            }
        }
        __syncthreads();
    }

    // epilogue: scatter to original node rows
    #pragma unroll
    for (int r = 0; r < 8; ++r) {
        int m = ty + 8 * r;
        if (m < rows) {
            float4* dst = (float4*)(out + (long long)s_cidx[m] * EMBED + tx * 4);
            *dst = make_float4(acc[r][0], acc[r][1], acc[r][2], acc[r][3]);
        }
    }
}

// ---------------------------------------------------------------------------
// kernel_launch
// inputs (metadata order): node_ids, node_tids, type_ids, feat0, W0,
//                          node_embed_table
// ---------------------------------------------------------------------------
extern "C" void kernel_launch(void* const* d_in, const int* in_sizes, int n_in,
                              void* d_out, int out_size)
{
    const void*  node_ids    = d_in[0];
    const void*  node_tids   = d_in[1];
    const void*  type_ids    = d_in[2];
    const float* feat0       = (const float*)d_in[3];
    const float* W0          = (const float*)d_in[4];
    const float* embed_table = (const float*)d_in[5];
    float* out = (float*)d_out;

    const int N = in_sizes[0];

    k0_detect_reset<<<1, 1>>>(node_ids);

    int blocks1 = (N + 255) / 256;
    k1_compact_embed<<<blocks1, 256>>>(node_ids, node_tids, embed_table, out, N);

    int blocks2 = (N + TILE_M - 1) / TILE_M;   // covers worst case (all tid==0)
    k2_proj_gemm<<<blocks2, 256>>>(type_ids, feat0, W0, out);
}

// round 3
// speedup vs baseline: 1.8354x; 1.8354x over previous
#include <cuda_runtime.h>
#include <cuda_bf16.h>
#include <cstdint>

// ---------------------------------------------------------------------------
// RelGraphEmbedLayer:
//   out[i] = feat0[type_ids[i]] @ W0           if node_tids[i] == 0
//   out[i] = node_embed_table[node_ids[i]]      if node_tids[i] == 1
//
// K0: dtype detect + counter reset
// K1: warp-aggregated compaction + fused embedding gather-copy
// K2: mma.sync (HMMA) bf16 GEMM, fp32 split hi/lo 3-pass, fragment-order smem
//     (tcgen05 is unavailable: harness compiles PTX at compute_103 baseline)
// ---------------------------------------------------------------------------

#define D_IN   256
#define EMBED  128
#define TILE_M 128
#define KCHUNK 32

__device__ int g_count;
__device__ int g_is64;
__device__ int g_compact[1100000];

__device__ __forceinline__ long long load_idx(const void* p, int i, int is64) {
    if (is64) return ((const long long*)p)[i];
    return (long long)((const int*)p)[i];
}

// ---------------------------------------------------------------------------
__global__ void k0_detect_reset(const void* node_ids) {
    const unsigned* w = (const unsigned*)node_ids;
    int is64 = 1;
    #pragma unroll
    for (int k = 0; k < 8; ++k)
        if (w[2 * k + 1] != 0u) { is64 = 0; break; }
    g_is64 = is64;
    g_count = 0;
}

// ---------------------------------------------------------------------------
__global__ __launch_bounds__(256) void k1_compact_embed(
    const void* __restrict__ node_ids,
    const void* __restrict__ node_tids,
    const float* __restrict__ table,
    float* __restrict__ out,
    int N)
{
    const int is64 = g_is64;
    const int base = blockIdx.x * 256;
    const int t    = threadIdx.x;
    const int lane = t & 31;
    const int wid  = t >> 5;
    const int i    = base + t;

    bool is0 = false;
    if (i < N) is0 = (load_idx(node_tids, i, is64) == 0);
    unsigned m = __ballot_sync(0xffffffffu, is0);
    int cnt  = __popc(m);
    int rank = __popc(m & ((1u << lane) - 1u));
    int wbase = 0;
    if (lane == 0 && cnt) wbase = atomicAdd(&g_count, cnt);
    wbase = __shfl_sync(0xffffffffu, wbase, 0);
    if (is0) g_compact[wbase + rank] = i;

    #pragma unroll
    for (int j = wid; j < 256; j += 8) {
        int ii = base + j;
        if (ii < N) {
            if (load_idx(node_tids, ii, is64) == 1) {
                long long nid = load_idx(node_ids, ii, is64);
                const float4* src = (const float4*)(table + nid * (long long)EMBED);
                float4*       dst = (float4*)(out + (long long)ii * EMBED);
                dst[lane] = src[lane];
            }
        }
    }
}

// ---------------------------------------------------------------------------
// bf16 hi/lo split helpers
// ---------------------------------------------------------------------------
__device__ __forceinline__ void split2(float x, float y, unsigned& hi, unsigned& lo) {
    __nv_bfloat162 h = __floats2bfloat162_rn(x, y);
    float rx = x - __bfloat162float(__low2bfloat16(h));
    float ry = y - __bfloat162float(__high2bfloat16(h));
    __nv_bfloat162 l = __floats2bfloat162_rn(rx, ry);
    hi = *(unsigned*)&h;
    lo = *(unsigned*)&l;
}

__device__ __forceinline__ void mma16816(float* d, const uint4& a, const uint2& b) {
    asm volatile(
        "mma.sync.aligned.m16n8k16.row.col.f32.bf16.bf16.f32 "
        "{%0,%1,%2,%3}, {%4,%5,%6,%7}, {%8,%9}, {%0,%1,%2,%3};"
        : "+f"(d[0]), "+f"(d[1]), "+f"(d[2]), "+f"(d[3])
        : "r"(a.x), "r"(a.y), "r"(a.z), "r"(a.w), "r"(b.x), "r"(b.y));
}

// ---------------------------------------------------------------------------
// K2: 128x128x256 per block, 256 threads = 8 warps (2x4), warp tile 64x32.
// Smem holds fragment-order tiles:
//   sA*[ (tm*2+tk)*32 + lane ] : uint4 = A-frag regs a0..a3 of 16x16 tile
//   sB*[ (tk*16+tn)*32 + lane ] : uint2 = B-frag regs b0..b1 of 16x8 tile
// ---------------------------------------------------------------------------
__global__ __launch_bounds__(256) void k2_proj_gemm(
    const void*  __restrict__ type_ids,
    const float* __restrict__ feat0,
    const float* __restrict__ W0,
    float* __restrict__ out)
{
    __shared__ uint4 sAH[512], sAL[512];       // 8KB each
    __shared__ uint2 sBH[1024], sBL[1024];     // 8KB each
    __shared__ int   s_cidx[TILE_M];
    __shared__ int   s_ridx[TILE_M];

    const int count = g_count;
    const int m0 = blockIdx.x * TILE_M;
    if (m0 >= count) return;
    const int rows = min(TILE_M, count - m0);

    const int is64 = g_is64;
    const int t    = threadIdx.x;
    const int lane = t & 31;
    const int wid  = t >> 5;
    const int warp_m = wid >> 2;     // 0..1
    const int warp_n = wid & 3;      // 0..3

    if (t < TILE_M) {
        int src  = (t < rows) ? (m0 + t) : m0;
        int cidx = g_compact[src];
        s_cidx[t] = cidx;
        s_ridx[t] = (int)load_idx(type_ids, cidx, is64);
    }
    __syncthreads();

    // staging identities
    const int tidf = t & 31;
    const int sg   = tidf >> 2;      // group (row within tile / col within B tile)
    const int stc  = tidf & 3;       // thread-in-group
    const int tmA  = t >> 5;         // A: tile_m 0..7
    const int tnB  = t >> 5;         // B: tile_n base 0..7 (and +8)

    const int ra0 = tmA * 16 + sg;
    const int ra1 = ra0 + 8;
    const float* ap0 = feat0 + (size_t)s_ridx[ra0] * D_IN;
    const float* ap1 = feat0 + (size_t)s_ridx[ra1] * D_IN;

    float acc[4][4][4];
    #pragma unroll
    for (int a = 0; a < 4; ++a)
        #pragma unroll
        for (int b = 0; b < 4; ++b)
            #pragma unroll
            for (int c = 0; c < 4; ++c) acc[a][b][c] = 0.0f;

    for (int kk = 0; kk < D_IN; kk += KCHUNK) {
        if (kk) __syncthreads();

        // ---- stage A: 2 k-tiles, write one uint4 fragment per (tm, tk, lane)
        #pragma unroll
        for (int tk = 0; tk < 2; ++tk) {
            const int k0 = kk + tk * 16 + stc * 2;
            float2 f00 = *(const float2*)(ap0 + k0);
            float2 f10 = *(const float2*)(ap1 + k0);
            float2 f01 = *(const float2*)(ap0 + k0 + 8);
            float2 f11 = *(const float2*)(ap1 + k0 + 8);
            uint4 H, L;
            split2(f00.x, f00.y, H.x, L.x);
            split2(f10.x, f10.y, H.y, L.y);
            split2(f01.x, f01.y, H.z, L.z);
            split2(f11.x, f11.y, H.w, L.w);
            const int idx = (tmA * 2 + tk) * 32 + tidf;
            sAH[idx] = H;
            sAL[idx] = L;
        }

        // ---- stage B: 2 n-groups x 2 k-tiles, uint2 fragment per (tk, tn, lane)
        #pragma unroll
        for (int q = 0; q < 2; ++q) {
            const int tn = tnB + 8 * q;
            const int n  = tn * 8 + sg;
            #pragma unroll
            for (int tk = 0; tk < 2; ++tk) {
                const int kb = kk + tk * 16 + stc * 2;
                float b00 = W0[(size_t)kb * EMBED + n];
                float b01 = W0[(size_t)(kb + 1) * EMBED + n];
                float b10 = W0[(size_t)(kb + 8) * EMBED + n];
                float b11 = W0[(size_t)(kb + 9) * EMBED + n];
                uint2 H, L;
                split2(b00, b01, H.x, L.x);
                split2(b10, b11, H.y, L.y);
                const int idx = (tk * 16 + tn) * 32 + tidf;
                sBH[idx] = H;
                sBL[idx] = L;
            }
        }
        __syncthreads();

        // ---- mma: 2 k-steps x (4 mt x 4 nt) x 3 passes
        #pragma unroll
        for (int ks = 0; ks < 2; ++ks) {
            uint2 bh[4], bl[4];
            #pragma unroll
            for (int nt = 0; nt < 4; ++nt) {
                const int idx = (ks * 16 + warp_n * 4 + nt) * 32 + lane;
                bh[nt] = sBH[idx];
                bl[nt] = sBL[idx];
            }
            #pragma unroll
            for (int mt = 0; mt < 4; ++mt) {
                const int idx = ((warp_m * 4 + mt) * 2 + ks) * 32 + lane;
                uint4 ah = sAH[idx];
                uint4 al = sAL[idx];
                #pragma unroll
                for (int nt = 0; nt < 4; ++nt) {
                    mma16816(acc[mt][nt], ah, bh[nt]);
                    mma16816(acc[mt][nt], al, bh[nt]);
                    mma16816(acc[mt][nt], ah, bl[nt]);
                }
            }
        }
    }

    // ---- epilogue: scatter from fragment layout
    const int g  = lane >> 2;
    const int tc = lane & 3;
    #pragma unroll
    for (int mt = 0; mt < 4; ++mt) {
        const int row0 = warp_m * 64 + mt * 16 + g;
        const int row1 = row0 + 8;
        float* o0 = (row0 < rows) ? (out + (size_t)s_cidx[row0] * EMBED) : nullptr;
        float* o1 = (row1 < rows) ? (out + (size_t)s_cidx[row1] * EMBED) : nullptr;
        #pragma unroll
        for (int nt = 0; nt < 4; ++nt) {
            const int col = warp_n * 32 + nt * 8 + tc * 2;
            if (o0) *(float2*)(o0 + col) = make_float2(acc[mt][nt][0], acc[mt][nt][1]);
            if (o1) *(float2*)(o1 + col) = make_float2(acc[mt][nt][2], acc[mt][nt][3]);
        }
    }
}

// ---------------------------------------------------------------------------
extern "C" void kernel_launch(void* const* d_in, const int* in_sizes, int n_in,
                              void* d_out, int out_size)
{
    const void*  node_ids    = d_in[0];
    const void*  node_tids   = d_in[1];
    const void*  type_ids    = d_in[2];
    const float* feat0       = (const float*)d_in[3];
    const float* W0          = (const float*)d_in[4];
    const float* embed_table = (const float*)d_in[5];
    float* out = (float*)d_out;

    const int N = in_sizes[0];

    k0_detect_reset<<<1, 1>>>(node_ids);

    int blocks1 = (N + 255) / 256;
    k1_compact_embed<<<blocks1, 256>>>(node_ids, node_tids, embed_table, out, N);

    int blocks2 = (N + TILE_M - 1) / TILE_M;
    k2_proj_gemm<<<blocks2, 256>>>(type_ids, feat0, W0, out);
}